// round 2
// baseline (speedup 1.0000x reference)
#include <cuda_runtime.h>
#include <cuda_bf16.h>
#include <math_constants.h>

// Nearest-radar-voxel lookup + sigmoid(saliency) gather.
// N radar points (<=5120), V lidar queries. Brute force over padded radar set.
// Rounding carefully mirrors the reference:
//   l2/r2 : round(x*x) + round(y*y) + round(z*z), rounded per add (NO fma)
//   cross : fma accumulation chain (K=3 GEMM style)
//   dist  : round( (l2+r2) - 2*cross )  -> fmaf(-2, c, l2+r2), 2c exact

#define MAXN 5120          // N=5000 padded to 5*1024
#define TILE 1024          // radar points per shared-memory tile
#define BLK  256

__device__ float4 g_pts[MAXN];   // {rx, ry, rz, r2}
__device__ float  g_sal[MAXN];   // sigmoid(0.6*|f0| + 0.4*f1)

__device__ __forceinline__ float sum_sq_ref(float x, float y, float z) {
    // Matches jnp.sum(c*c): per-op rounding, no contraction.
    float x2 = __fmul_rn(x, x);
    float y2 = __fmul_rn(y, y);
    float z2 = __fmul_rn(z, z);
    return __fadd_rn(__fadd_rn(x2, y2), z2);
}

__global__ void prep_kernel(const float* __restrict__ feat,
                            const float* __restrict__ rcoords, int N) {
    int n = blockIdx.x * blockDim.x + threadIdx.x;
    if (n >= MAXN) return;
    if (n < N) {
        float rx = rcoords[3 * n + 0];
        float ry = rcoords[3 * n + 1];
        float rz = rcoords[3 * n + 2];
        float r2 = sum_sq_ref(rx, ry, rz);
        g_pts[n] = make_float4(rx, ry, rz, r2);
        float f0 = feat[64 * n + 0];
        float f1 = feat[64 * n + 1];
        // round(0.6*|f0|) + round(0.4*f1), rounded add — mirrors reference.
        float s = __fadd_rn(__fmul_rn(0.6f, fabsf(f0)), __fmul_rn(0.4f, f1));
        g_sal[n] = 1.0f / (1.0f + expf(-s));
    } else {
        // padding: distance evaluates to +inf, never selected
        g_pts[n] = make_float4(0.0f, 0.0f, 0.0f, CUDART_INF_F);
        g_sal[n] = 0.0f;
    }
}

__global__ void __launch_bounds__(BLK) nn_kernel(
    const float* __restrict__ lcoords,
    float* __restrict__ out, int V) {
    __shared__ float4 s_pts[TILE];

    int v = blockIdx.x * blockDim.x + threadIdx.x;
    float x = 0.f, y = 0.f, z = 0.f, l2 = 0.f;
    if (v < V) {
        x = lcoords[3 * v + 0];
        y = lcoords[3 * v + 1];
        z = lcoords[3 * v + 2];
        l2 = sum_sq_ref(x, y, z);
    }

    // 4 independent argmin chains (radar index n ≡ c mod 4) to break the
    // FSETP->SEL dependence chain. Strict '<' keeps first occurrence within
    // each ascending chain; merge below tie-breaks on index.
    float best0 = CUDART_INF_F, best1 = CUDART_INF_F;
    float best2 = CUDART_INF_F, best3 = CUDART_INF_F;
    int   i0 = 0x7fffffff, i1 = 0x7fffffff, i2 = 0x7fffffff, i3 = 0x7fffffff;

    for (int base = 0; base < MAXN; base += TILE) {
        __syncthreads();
        #pragma unroll
        for (int t = threadIdx.x; t < TILE; t += BLK)
            s_pts[t] = g_pts[base + t];
        __syncthreads();

        #pragma unroll 2
        for (int j = 0; j < TILE; j += 4) {
            float4 p0 = s_pts[j + 0];
            float4 p1 = s_pts[j + 1];
            float4 p2 = s_pts[j + 2];
            float4 p3 = s_pts[j + 3];

            // cross: K=3 GEMM-style fma chain; fma(x,px,0)==round(x*px).
            float c0 = fmaf(z, p0.z, fmaf(y, p0.y, __fmul_rn(x, p0.x)));
            float c1 = fmaf(z, p1.z, fmaf(y, p1.y, __fmul_rn(x, p1.x)));
            float c2 = fmaf(z, p2.z, fmaf(y, p2.y, __fmul_rn(x, p2.x)));
            float c3 = fmaf(z, p3.z, fmaf(y, p3.y, __fmul_rn(x, p3.x)));

            // s = round(l2 + r2); d = round(s - 2*cross) (2c exact -> fma ok)
            float s0 = __fadd_rn(l2, p0.w);
            float s1 = __fadd_rn(l2, p1.w);
            float s2 = __fadd_rn(l2, p2.w);
            float s3 = __fadd_rn(l2, p3.w);
            float d0 = fmaf(-2.0f, c0, s0);
            float d1 = fmaf(-2.0f, c1, s1);
            float d2 = fmaf(-2.0f, c2, s2);
            float d3 = fmaf(-2.0f, c3, s3);

            if (d0 < best0) { best0 = d0; i0 = base + j + 0; }
            if (d1 < best1) { best1 = d1; i1 = base + j + 1; }
            if (d2 < best2) { best2 = d2; i2 = base + j + 2; }
            if (d3 < best3) { best3 = d3; i3 = base + j + 3; }
        }
    }

    // Merge the 4 chains; ties resolved toward the smaller radar index to
    // match jnp.argmin's first-occurrence semantics.
    float B = best0; int I = i0;
    if (best1 < B || (best1 == B && i1 < I)) { B = best1; I = i1; }
    if (best2 < B || (best2 == B && i2 < I)) { B = best2; I = i2; }
    if (best3 < B || (best3 == B && i3 < I)) { B = best3; I = i3; }

    if (v < V)
        out[v] = g_sal[I];
}

extern "C" void kernel_launch(void* const* d_in, const int* in_sizes, int n_in,
                              void* d_out, int out_size) {
    const float* feat    = (const float*)d_in[0];   // [N, 64]
    const float* lcoords = (const float*)d_in[1];   // [V, 3]
    const float* rcoords = (const float*)d_in[2];   // [N, 3]
    float* out = (float*)d_out;                     // [V]

    int N = in_sizes[0] / 64;
    int V = in_sizes[1] / 3;

    prep_kernel<<<(MAXN + BLK - 1) / BLK, BLK>>>(feat, rcoords, N);
    nn_kernel<<<(V + BLK - 1) / BLK, BLK>>>(lcoords, out, V);
}

// round 3
// speedup vs baseline: 1.3885x; 1.3885x over previous
#include <cuda_runtime.h>
#include <cuda_bf16.h>
#include <math_constants.h>

// Nearest-radar-voxel lookup + sigmoid(saliency) gather.
// Radar set split RSPLIT ways across blockIdx.y for 4x grid parallelism;
// per-slice (dist,idx) packed keys merged by a tiny gather kernel.
// Rounding mirrors the reference exactly:
//   l2/r2 : round(x*x)+round(y*y)+round(z*z), rounded adds (NO fma)
//   cross : fma accumulation chain (K=3 GEMM style)
//   dist  : round( round(l2+r2) - 2*cross )  -> fmaf(-2,c, s), 2c exact

#define MAXN   5120          // N=5000 padded
#define RSPLIT 4
#define SLICE  (MAXN / RSPLIT)   // 1280 points per slice (20KB shared)
#define BLK    256
#define MAXV   51200

__device__ float4 g_pts[MAXN];   // {rx, ry, rz, r2}
__device__ float  g_sal[MAXN];   // sigmoid(0.6*|f0| + 0.4*f1)
__device__ unsigned long long g_keys[RSPLIT][MAXV];  // (ordered-dist | idx)

__device__ __forceinline__ float sum_sq_ref(float x, float y, float z) {
    // Matches jnp.sum(c*c): per-op rounding, no contraction.
    float x2 = __fmul_rn(x, x);
    float y2 = __fmul_rn(y, y);
    float z2 = __fmul_rn(z, z);
    return __fadd_rn(__fadd_rn(x2, y2), z2);
}

__global__ void prep_kernel(const float* __restrict__ feat,
                            const float* __restrict__ rcoords, int N) {
    int n = blockIdx.x * blockDim.x + threadIdx.x;
    if (n >= MAXN) return;
    if (n < N) {
        float rx = rcoords[3 * n + 0];
        float ry = rcoords[3 * n + 1];
        float rz = rcoords[3 * n + 2];
        g_pts[n] = make_float4(rx, ry, rz, sum_sq_ref(rx, ry, rz));
        float f0 = feat[64 * n + 0];
        float f1 = feat[64 * n + 1];
        float s = __fadd_rn(__fmul_rn(0.6f, fabsf(f0)), __fmul_rn(0.4f, f1));
        g_sal[n] = 1.0f / (1.0f + expf(-s));
    } else {
        g_pts[n] = make_float4(0.0f, 0.0f, 0.0f, CUDART_INF_F);  // never wins
        g_sal[n] = 0.0f;
    }
}

__global__ void __launch_bounds__(BLK) nn_kernel(
    const float* __restrict__ lcoords, int V) {
    __shared__ float4 s_pts[SLICE];

    const int r    = blockIdx.y;
    const int base = r * SLICE;

    #pragma unroll
    for (int t = threadIdx.x; t < SLICE; t += BLK)
        s_pts[t] = g_pts[base + t];
    __syncthreads();

    const int v = blockIdx.x * BLK + threadIdx.x;
    if (v >= V) return;

    const float x  = lcoords[3 * v + 0];
    const float y  = lcoords[3 * v + 1];
    const float z  = lcoords[3 * v + 2];
    const float l2 = sum_sq_ref(x, y, z);

    // 4 independent argmin chains (j mod 4) to break FSETP->SEL serialization.
    float best0 = CUDART_INF_F, best1 = CUDART_INF_F;
    float best2 = CUDART_INF_F, best3 = CUDART_INF_F;
    int   i0 = 0x7fffffff, i1 = 0x7fffffff, i2 = 0x7fffffff, i3 = 0x7fffffff;

    #pragma unroll 2
    for (int j = 0; j < SLICE; j += 4) {
        float4 p0 = s_pts[j + 0];
        float4 p1 = s_pts[j + 1];
        float4 p2 = s_pts[j + 2];
        float4 p3 = s_pts[j + 3];

        float c0 = fmaf(z, p0.z, fmaf(y, p0.y, __fmul_rn(x, p0.x)));
        float c1 = fmaf(z, p1.z, fmaf(y, p1.y, __fmul_rn(x, p1.x)));
        float c2 = fmaf(z, p2.z, fmaf(y, p2.y, __fmul_rn(x, p2.x)));
        float c3 = fmaf(z, p3.z, fmaf(y, p3.y, __fmul_rn(x, p3.x)));

        float s0 = __fadd_rn(l2, p0.w);
        float s1 = __fadd_rn(l2, p1.w);
        float s2 = __fadd_rn(l2, p2.w);
        float s3 = __fadd_rn(l2, p3.w);
        float d0 = fmaf(-2.0f, c0, s0);
        float d1 = fmaf(-2.0f, c1, s1);
        float d2 = fmaf(-2.0f, c2, s2);
        float d3 = fmaf(-2.0f, c3, s3);

        if (d0 < best0) { best0 = d0; i0 = base + j + 0; }
        if (d1 < best1) { best1 = d1; i1 = base + j + 1; }
        if (d2 < best2) { best2 = d2; i2 = base + j + 2; }
        if (d3 < best3) { best3 = d3; i3 = base + j + 3; }
    }

    // Merge chains; ties -> smaller radar index (jnp.argmin first occurrence).
    float B = best0; int I = i0;
    if (best1 < B || (best1 == B && i1 < I)) { B = best1; I = i1; }
    if (best2 < B || (best2 == B && i2 < I)) { B = best2; I = i2; }
    if (best3 < B || (best3 == B && i3 < I)) { B = best3; I = i3; }

    // Order-preserving float->uint map, pack with index (low bits = idx so
    // equal distances resolve to the smaller index under u64 min).
    unsigned u = __float_as_uint(B);
    u = (u & 0x80000000u) ? ~u : (u | 0x80000000u);
    g_keys[r][v] = ((unsigned long long)u << 32) | (unsigned)I;
}

__global__ void gather_kernel(float* __restrict__ out, int V) {
    int v = blockIdx.x * blockDim.x + threadIdx.x;
    if (v >= V) return;
    unsigned long long k0 = g_keys[0][v];
    unsigned long long k1 = g_keys[1][v];
    unsigned long long k2 = g_keys[2][v];
    unsigned long long k3 = g_keys[3][v];
    unsigned long long k = min(min(k0, k1), min(k2, k3));
    out[v] = g_sal[(unsigned)k];
}

extern "C" void kernel_launch(void* const* d_in, const int* in_sizes, int n_in,
                              void* d_out, int out_size) {
    const float* feat    = (const float*)d_in[0];   // [N, 64]
    const float* lcoords = (const float*)d_in[1];   // [V, 3]
    const float* rcoords = (const float*)d_in[2];   // [N, 3]
    float* out = (float*)d_out;                     // [V]

    int N = in_sizes[0] / 64;
    int V = in_sizes[1] / 3;

    int gx = (V + BLK - 1) / BLK;
    prep_kernel<<<(MAXN + BLK - 1) / BLK, BLK>>>(feat, rcoords, N);
    nn_kernel<<<dim3(gx, RSPLIT), BLK>>>(lcoords, V);
    gather_kernel<<<gx, BLK>>>(out, V);
}

// round 4
// speedup vs baseline: 2.3472x; 1.6905x over previous
#include <cuda_runtime.h>
#include <cuda_bf16.h>
#include <math_constants.h>

// Grid-accelerated nearest-radar-voxel lookup + sigmoid(saliency) gather.
// 8x8x8 uniform grid over [0,100]^3 (cell 12.5). Each query scans its 3x3x3
// cell neighborhood; any excluded point has true dist^2 > 156.25, so if the
// neighborhood best (computed with reference rounding, abs err << 1) is
// < 155.25 the result is provably the global argmin. Otherwise (prob ~0)
// fall back to a full brute-force scan. Distance arithmetic is bit-identical
// to the reference:
//   l2/r2 : round(x*x)+round(y*y)+round(z*z), rounded adds (NO fma)
//   cross : fma accumulation chain (K=3 GEMM style)
//   dist  : fmaf(-2, c, round(l2+r2))   (2c exact -> one final rounding)
// argmin ties: u64 min over (ordered-dist | orig idx) keys == first occurrence.

#define GDIM   8
#define NCELL  (GDIM * GDIM * GDIM)
#define CELLW  12.5f
#define MAXNPT 8192
#define PREPB  256
#define QBLK   128

__device__ float4 g_pts[MAXNPT];    // raw order: {x,y,z,r2}
__device__ float  g_sal[MAXNPT];    // sigmoid(0.6*|f0|+0.4*f1), raw index
__device__ int    g_cell[MAXNPT];
__device__ int    g_count[NCELL];
__device__ int    g_start[NCELL + 1];
__device__ int    g_cursor[NCELL];
__device__ float4 g_spts[MAXNPT];   // grid-sorted points
__device__ int    g_sidx[MAXNPT];   // grid-sorted -> original index

__device__ __forceinline__ float sum_sq_ref(float x, float y, float z) {
    float x2 = __fmul_rn(x, x);
    float y2 = __fmul_rn(y, y);
    float z2 = __fmul_rn(z, z);
    return __fadd_rn(__fadd_rn(x2, y2), z2);
}

__device__ __forceinline__ int cell_coord(float x) {
    int c = (int)(x * (1.0f / CELLW));
    return min(max(c, 0), GDIM - 1);
}

__global__ void zero_kernel() {
    g_count[threadIdx.x] = 0;
}

__global__ void prep_kernel(const float* __restrict__ feat,
                            const float* __restrict__ rcoords, int N) {
    int n = blockIdx.x * blockDim.x + threadIdx.x;
    if (n >= N) return;
    float rx = rcoords[3 * n + 0];
    float ry = rcoords[3 * n + 1];
    float rz = rcoords[3 * n + 2];
    g_pts[n] = make_float4(rx, ry, rz, sum_sq_ref(rx, ry, rz));
    int c = (cell_coord(rz) * GDIM + cell_coord(ry)) * GDIM + cell_coord(rx);
    g_cell[n] = c;
    atomicAdd(&g_count[c], 1);
    float f0 = feat[64 * n + 0];
    float f1 = feat[64 * n + 1];
    float s = __fadd_rn(__fmul_rn(0.6f, fabsf(f0)), __fmul_rn(0.4f, f1));
    g_sal[n] = 1.0f / (1.0f + expf(-s));
}

__global__ void scan_kernel() {
    __shared__ int tmp[NCELL];
    int t = threadIdx.x;
    int cnt = g_count[t];
    tmp[t] = cnt;
    __syncthreads();
    // Hillis-Steele inclusive scan over 512 elements
    for (int off = 1; off < NCELL; off <<= 1) {
        int add = (t >= off) ? tmp[t - off] : 0;
        __syncthreads();
        tmp[t] += add;
        __syncthreads();
    }
    int incl = tmp[t];
    g_start[t + 1] = incl;
    if (t == 0) g_start[0] = 0;
    g_cursor[t] = incl - cnt;   // exclusive
}

__global__ void scatter_kernel(int N) {
    int n = blockIdx.x * blockDim.x + threadIdx.x;
    if (n >= N) return;
    int pos = atomicAdd(&g_cursor[g_cell[n]], 1);
    g_spts[pos] = g_pts[n];
    g_sidx[pos] = n;
}

// Order-preserving float -> uint (ascending).
__device__ __forceinline__ unsigned float_ordered(float f) {
    unsigned u = __float_as_uint(f);
    return (u & 0x80000000u) ? ~u : (u | 0x80000000u);
}

// Two threads per query: halves alternate spans, merged via shfl_xor(1).
__global__ void __launch_bounds__(QBLK) query_kernel(
    const float* __restrict__ lcoords, float* __restrict__ out,
    int V, int N) {
    int t    = blockIdx.x * QBLK + threadIdx.x;
    int v    = t >> 1;
    int half = t & 1;
    bool valid = (v < V);
    int vc = valid ? v : (V - 1);   // out-of-range threads duplicate last query
                                    // (keeps warp lanes converged for shfl)

    float x = lcoords[3 * vc + 0];
    float y = lcoords[3 * vc + 1];
    float z = lcoords[3 * vc + 2];
    float l2 = sum_sq_ref(x, y, z);

    int cx = cell_coord(x), cy = cell_coord(y), cz = cell_coord(z);
    int x0 = max(cx - 1, 0), x1 = min(cx + 1, GDIM - 1);
    int y0 = max(cy - 1, 0), y1 = min(cy + 1, GDIM - 1);
    int z0 = max(cz - 1, 0), z1 = min(cz + 1, GDIM - 1);

    unsigned long long best = ~0ull;
    int sid = 0;
    for (int dz = z0; dz <= z1; dz++) {
        for (int dy = y0; dy <= y1; dy++) {
            bool mine = ((sid++) & 1) == half;
            if (!mine) continue;
            int row = (dz * GDIM + dy) * GDIM;
            int s = g_start[row + x0];
            int e = g_start[row + x1 + 1];   // x-cells are id-contiguous
            for (int p = s; p < e; p++) {
                float4 pt = g_spts[p];
                float c = fmaf(z, pt.z, fmaf(y, pt.y, __fmul_rn(x, pt.x)));
                float d = fmaf(-2.0f, c, __fadd_rn(l2, pt.w));
                unsigned long long key =
                    ((unsigned long long)float_ordered(d) << 32) |
                    (unsigned)g_sidx[p];
                best = min(best, key);
            }
        }
    }
    best = min(best, __shfl_xor_sync(0xffffffffu, best, 1));

    // Safe-finality check: excluded points have true dist^2 > 156.25; with
    // >=1.0 slack for rounding of computed distances, best < 155.25 is final.
    // ordered(155.25f) = 0xC31B4000.
    if ((unsigned)(best >> 32) >= 0xC31B4000u) {
        // Fallback: full brute-force scan (provably correct, ~never taken).
        for (int p = half; p < N; p += 2) {
            float4 pt = g_spts[p];
            float c = fmaf(z, pt.z, fmaf(y, pt.y, __fmul_rn(x, pt.x)));
            float d = fmaf(-2.0f, c, __fadd_rn(l2, pt.w));
            unsigned long long key =
                ((unsigned long long)float_ordered(d) << 32) |
                (unsigned)g_sidx[p];
            best = min(best, key);
        }
        best = min(best, __shfl_xor_sync(0xffffffffu, best, 1));
    }

    if (valid && half == 0)
        out[v] = g_sal[(unsigned)best];
}

extern "C" void kernel_launch(void* const* d_in, const int* in_sizes, int n_in,
                              void* d_out, int out_size) {
    const float* feat    = (const float*)d_in[0];   // [N, 64]
    const float* lcoords = (const float*)d_in[1];   // [V, 3]
    const float* rcoords = (const float*)d_in[2];   // [N, 3]
    float* out = (float*)d_out;                     // [V]

    int N = in_sizes[0] / 64;
    int V = in_sizes[1] / 3;

    zero_kernel<<<1, NCELL>>>();
    prep_kernel<<<(N + PREPB - 1) / PREPB, PREPB>>>(feat, rcoords, N);
    scan_kernel<<<1, NCELL>>>();
    scatter_kernel<<<(N + PREPB - 1) / PREPB, PREPB>>>(N);

    int qthreads = 2 * V;
    query_kernel<<<(qthreads + QBLK - 1) / QBLK, QBLK>>>(lcoords, out, V, N);
}

// round 5
// speedup vs baseline: 3.3360x; 1.4213x over previous
#include <cuda_runtime.h>
#include <cuda_bf16.h>
#include <math_constants.h>

// Grid-accelerated NN lookup + sigmoid(saliency) gather, both sides binned.
// 8^3 grid over [0,100]^3 (cell 12.5). Query kernel: one block per cell;
// the 3x3x3 candidate neighborhood is staged to shared memory once and all
// of the cell's queries scan it in lockstep (broadcast LDS). Excluded points
// have true dist^2 > 156.25; best < 155.25 (with rounding slack) is provably
// final, else per-thread full brute-force fallback.
// Distance arithmetic bit-identical to the reference:
//   l2/r2 : round(x*x)+round(y*y)+round(z*z), rounded adds (NO fma)
//   cross : fma chain (K=3 GEMM style);  dist : fmaf(-2,c, round(l2+r2))
// argmin ties: u64 min over (ordered-dist | orig idx) == first occurrence,
// independent of candidate scan order.

#define GDIM    8
#define NCELL   (GDIM * GDIM * GDIM)
#define CELLW   12.5f
#define MAXNPT  8192
#define MAXV    65536
#define CAP     1024      // candidate cap per neighborhood (smem)
#define PB      256
#define QBLK    128

__device__ float4 g_pts[MAXNPT];       // raw order {x,y,z,r2}
__device__ float  g_sal[MAXNPT];
__device__ int    g_cell[MAXNPT];
__device__ int    g_count[NCELL];
__device__ int    g_start[NCELL + 1];
__device__ int    g_cursor[NCELL];
__device__ float4 g_spts[MAXNPT];      // grid-sorted points
__device__ int    g_sidx[MAXNPT];      // sorted -> original index
__device__ int    g_qcell[MAXV];
__device__ int    g_qcount[NCELL];
__device__ int    g_qstart[NCELL + 1];
__device__ int    g_qcursor[NCELL];
__device__ int    g_qidx[MAXV];        // cell-sorted query ids

__device__ __forceinline__ float sum_sq_ref(float x, float y, float z) {
    float x2 = __fmul_rn(x, x);
    float y2 = __fmul_rn(y, y);
    float z2 = __fmul_rn(z, z);
    return __fadd_rn(__fadd_rn(x2, y2), z2);
}

__device__ __forceinline__ int cell_coord(float x) {
    int c = (int)(x * (1.0f / CELLW));
    return min(max(c, 0), GDIM - 1);
}

__device__ __forceinline__ unsigned float_ordered(float f) {
    unsigned u = __float_as_uint(f);
    return (u & 0x80000000u) ? ~u : (u | 0x80000000u);
}

__global__ void init_kernel() {
    int t = threadIdx.x;             // 512 threads
    g_count[t] = 0;
    g_qcount[t] = 0;
}

// Fused: threads [0,N) build radar side; threads [N, N+V) count queries.
__global__ void prep_kernel(const float* __restrict__ feat,
                            const float* __restrict__ rcoords,
                            const float* __restrict__ lcoords,
                            int N, int V) {
    int t = blockIdx.x * blockDim.x + threadIdx.x;
    if (t < N) {
        int n = t;
        float rx = rcoords[3 * n + 0];
        float ry = rcoords[3 * n + 1];
        float rz = rcoords[3 * n + 2];
        g_pts[n] = make_float4(rx, ry, rz, sum_sq_ref(rx, ry, rz));
        int c = (cell_coord(rz) * GDIM + cell_coord(ry)) * GDIM + cell_coord(rx);
        g_cell[n] = c;
        atomicAdd(&g_count[c], 1);
        float f0 = feat[64 * n + 0];
        float f1 = feat[64 * n + 1];
        float s = __fadd_rn(__fmul_rn(0.6f, fabsf(f0)), __fmul_rn(0.4f, f1));
        g_sal[n] = 1.0f / (1.0f + expf(-s));
    } else if (t < N + V) {
        int v = t - N;
        float x = lcoords[3 * v + 0];
        float y = lcoords[3 * v + 1];
        float z = lcoords[3 * v + 2];
        int c = (cell_coord(z) * GDIM + cell_coord(y)) * GDIM + cell_coord(x);
        g_qcell[v] = c;
        atomicAdd(&g_qcount[c], 1);
    }
}

// One block, 512 threads: scan both histograms.
__global__ void scan_kernel() {
    __shared__ int tmp[NCELL];
    int t = threadIdx.x;

    int cnt = g_count[t];
    tmp[t] = cnt;
    __syncthreads();
    for (int off = 1; off < NCELL; off <<= 1) {
        int add = (t >= off) ? tmp[t - off] : 0;
        __syncthreads();
        tmp[t] += add;
        __syncthreads();
    }
    g_start[t + 1] = tmp[t];
    if (t == 0) g_start[0] = 0;
    g_cursor[t] = tmp[t] - cnt;
    __syncthreads();

    int qcnt = g_qcount[t];
    tmp[t] = qcnt;
    __syncthreads();
    for (int off = 1; off < NCELL; off <<= 1) {
        int add = (t >= off) ? tmp[t - off] : 0;
        __syncthreads();
        tmp[t] += add;
        __syncthreads();
    }
    g_qstart[t + 1] = tmp[t];
    if (t == 0) g_qstart[0] = 0;
    g_qcursor[t] = tmp[t] - qcnt;
}

// Fused scatter: radar points + query ids into cell-sorted order.
__global__ void scatter_kernel(int N, int V) {
    int t = blockIdx.x * blockDim.x + threadIdx.x;
    if (t < N) {
        int pos = atomicAdd(&g_cursor[g_cell[t]], 1);
        g_spts[pos] = g_pts[t];
        g_sidx[pos] = t;
    } else if (t < N + V) {
        int v = t - N;
        int pos = atomicAdd(&g_qcursor[g_qcell[v]], 1);
        g_qidx[pos] = v;
    }
}

__global__ void __launch_bounds__(QBLK) query_kernel(
    const float* __restrict__ lcoords, float* __restrict__ out, int N) {
    __shared__ float4 s_pts[CAP];
    __shared__ int    s_idx[CAP];

    const int cell = blockIdx.x;
    const int qs = g_qstart[cell];
    const int qe = g_qstart[cell + 1];
    if (qs == qe) return;

    const int cz = cell >> 6, cy = (cell >> 3) & 7, cx = cell & 7;
    const int x0 = max(cx - 1, 0), x1 = min(cx + 1, GDIM - 1);
    const int y0 = max(cy - 1, 0), y1 = min(cy + 1, GDIM - 1);
    const int z0 = max(cz - 1, 0), z1 = min(cz + 1, GDIM - 1);
    const int tid = threadIdx.x;

    // Total candidate count (all threads compute identically; broadcast LDG).
    int total = 0;
    for (int dz = z0; dz <= z1; dz++)
        for (int dy = y0; dy <= y1; dy++) {
            int row = (dz * GDIM + dy) * GDIM;
            total += g_start[row + x1 + 1] - g_start[row + x0];
        }

    const bool use_smem = (total <= CAP - 4);
    int padded = 0;
    if (use_smem) {
        int dst = 0;
        for (int dz = z0; dz <= z1; dz++)
            for (int dy = y0; dy <= y1; dy++) {
                int row = (dz * GDIM + dy) * GDIM;
                int s = g_start[row + x0];
                int len = g_start[row + x1 + 1] - s;
                for (int i = tid; i < len; i += QBLK) {
                    s_pts[dst + i] = g_spts[s + i];
                    s_idx[dst + i] = g_sidx[s + i];
                }
                dst += len;
            }
        padded = (total + 3) & ~3;
        if (tid < padded - total) {
            s_pts[total + tid] = make_float4(0.f, 0.f, 0.f, CUDART_INF_F);
            s_idx[total + tid] = 0;
        }
        __syncthreads();
    }

    for (int q = qs + tid; q < qe; q += QBLK) {
        const int v = g_qidx[q];
        const float x = lcoords[3 * v + 0];
        const float y = lcoords[3 * v + 1];
        const float z = lcoords[3 * v + 2];
        const float l2 = sum_sq_ref(x, y, z);

        unsigned long long b0 = ~0ull, b1 = ~0ull, b2 = ~0ull, b3 = ~0ull;
        if (use_smem) {
            for (int j = 0; j < padded; j += 4) {
                float4 p0 = s_pts[j + 0];
                float4 p1 = s_pts[j + 1];
                float4 p2 = s_pts[j + 2];
                float4 p3 = s_pts[j + 3];
                float c0 = fmaf(z, p0.z, fmaf(y, p0.y, __fmul_rn(x, p0.x)));
                float c1 = fmaf(z, p1.z, fmaf(y, p1.y, __fmul_rn(x, p1.x)));
                float c2 = fmaf(z, p2.z, fmaf(y, p2.y, __fmul_rn(x, p2.x)));
                float c3 = fmaf(z, p3.z, fmaf(y, p3.y, __fmul_rn(x, p3.x)));
                float d0 = fmaf(-2.0f, c0, __fadd_rn(l2, p0.w));
                float d1 = fmaf(-2.0f, c1, __fadd_rn(l2, p1.w));
                float d2 = fmaf(-2.0f, c2, __fadd_rn(l2, p2.w));
                float d3 = fmaf(-2.0f, c3, __fadd_rn(l2, p3.w));
                unsigned long long k0 =
                    ((unsigned long long)float_ordered(d0) << 32) | (unsigned)s_idx[j + 0];
                unsigned long long k1 =
                    ((unsigned long long)float_ordered(d1) << 32) | (unsigned)s_idx[j + 1];
                unsigned long long k2 =
                    ((unsigned long long)float_ordered(d2) << 32) | (unsigned)s_idx[j + 2];
                unsigned long long k3 =
                    ((unsigned long long)float_ordered(d3) << 32) | (unsigned)s_idx[j + 3];
                b0 = min(b0, k0); b1 = min(b1, k1);
                b2 = min(b2, k2); b3 = min(b3, k3);
            }
        }
        unsigned long long best = min(min(b0, b1), min(b2, b3));

        // Finality: excluded true dist^2 > 156.25; slack 1.0 for rounding.
        // ordered(155.25f) = 0xC31B4000.
        if ((unsigned)(best >> 32) >= 0xC31B4000u) {
            for (int p = 0; p < N; p++) {
                float4 pt = g_spts[p];
                float c = fmaf(z, pt.z, fmaf(y, pt.y, __fmul_rn(x, pt.x)));
                float d = fmaf(-2.0f, c, __fadd_rn(l2, pt.w));
                unsigned long long k =
                    ((unsigned long long)float_ordered(d) << 32) | (unsigned)g_sidx[p];
                best = min(best, k);
            }
        }
        out[v] = g_sal[(unsigned)best];
    }
}

extern "C" void kernel_launch(void* const* d_in, const int* in_sizes, int n_in,
                              void* d_out, int out_size) {
    const float* feat    = (const float*)d_in[0];   // [N, 64]
    const float* lcoords = (const float*)d_in[1];   // [V, 3]
    const float* rcoords = (const float*)d_in[2];   // [N, 3]
    float* out = (float*)d_out;                     // [V]

    int N = in_sizes[0] / 64;
    int V = in_sizes[1] / 3;
    int NV = N + V;

    init_kernel<<<1, NCELL>>>();
    prep_kernel<<<(NV + PB - 1) / PB, PB>>>(feat, rcoords, lcoords, N, V);
    scan_kernel<<<1, NCELL>>>();
    scatter_kernel<<<(NV + PB - 1) / PB, PB>>>(N, V);
    query_kernel<<<NCELL, QBLK>>>(lcoords, out, N);
}

// round 6
// speedup vs baseline: 4.3127x; 1.2928x over previous
#include <cuda_runtime.h>
#include <cuda_bf16.h>
#include <math_constants.h>

// Grid-accelerated NN lookup + sigmoid(saliency), fixed-capacity cell buckets.
// 8^3 grid over [0,100]^3 (cell 12.5). Pipeline: memset(counters) -> prep
// (bin radar points + queries straight into per-cell buckets via atomicAdd)
// -> query (block per cell: stage 3x3x3 neighborhood to smem, scan lockstep).
// Bucket order is nondeterministic but all reductions are order-invariant
// (u64 min over (ordered-dist | orig idx)); overflow paths fall back to full
// scans, so correctness never depends on bucket capacities.
// Distance arithmetic bit-identical to the reference:
//   l2/r2 : round(x*x)+round(y*y)+round(z*z), rounded adds (NO fma)
//   cross : fma chain (K=3 GEMM style);  dist : fmaf(-2,c, round(l2+r2))
// Excluded points (outside 3x3x3) have true dist^2 > 156.25; best < 155.25
// (rounding slack >= 1.0) is provably final, else full brute-force fallback.

#define GDIM   8
#define NCELL  (GDIM * GDIM * GDIM)
#define CELLW  12.5f
#define MAXNPT 8192
#define MAXV   65536
#define CAP_R  64
#define CAP_Q  192
#define SCAP   1024
#define PB     256
#define QBLK   128

__device__ int    g_counts[2 * NCELL];        // [0,512): radar, [512,1024): query
__device__ float4 g_pts[MAXNPT];              // raw order {x,y,z,r2} (fallback)
__device__ float  g_sal[MAXNPT];
__device__ float4 g_rbucket[NCELL * CAP_R];
__device__ int    g_rbidx[NCELL * CAP_R];
__device__ int    g_qbucket[NCELL * CAP_Q];   // query ids per cell
__device__ int    g_qcell[MAXV];              // query -> cell (overflow path)

__device__ __forceinline__ float sum_sq_ref(float x, float y, float z) {
    float x2 = __fmul_rn(x, x);
    float y2 = __fmul_rn(y, y);
    float z2 = __fmul_rn(z, z);
    return __fadd_rn(__fadd_rn(x2, y2), z2);
}

__device__ __forceinline__ int cell_coord(float x) {
    int c = (int)(x * (1.0f / CELLW));
    return min(max(c, 0), GDIM - 1);
}

__device__ __forceinline__ unsigned float_ordered(float f) {
    unsigned u = __float_as_uint(f);
    return (u & 0x80000000u) ? ~u : (u | 0x80000000u);
}

__global__ void prep_kernel(const float* __restrict__ feat,
                            const float* __restrict__ rcoords,
                            const float* __restrict__ lcoords,
                            int N, int V) {
    int t = blockIdx.x * blockDim.x + threadIdx.x;
    if (t < N) {
        int n = t;
        float rx = rcoords[3 * n + 0];
        float ry = rcoords[3 * n + 1];
        float rz = rcoords[3 * n + 2];
        float4 p = make_float4(rx, ry, rz, sum_sq_ref(rx, ry, rz));
        g_pts[n] = p;
        float f0 = feat[64 * n + 0];
        float f1 = feat[64 * n + 1];
        float s = __fadd_rn(__fmul_rn(0.6f, fabsf(f0)), __fmul_rn(0.4f, f1));
        g_sal[n] = 1.0f / (1.0f + expf(-s));
        int c = (cell_coord(rz) * GDIM + cell_coord(ry)) * GDIM + cell_coord(rx);
        int pos = atomicAdd(&g_counts[c], 1);
        if (pos < CAP_R) {
            g_rbucket[c * CAP_R + pos] = p;
            g_rbidx[c * CAP_R + pos] = n;
        }
    } else if (t < N + V) {
        int v = t - N;
        float x = lcoords[3 * v + 0];
        float y = lcoords[3 * v + 1];
        float z = lcoords[3 * v + 2];
        int c = (cell_coord(z) * GDIM + cell_coord(y)) * GDIM + cell_coord(x);
        g_qcell[v] = c;
        int pos = atomicAdd(&g_counts[NCELL + c], 1);
        if (pos < CAP_Q) g_qbucket[c * CAP_Q + pos] = v;
    }
}

// Scan the staged (or fallback) candidate set for one query.
__device__ __forceinline__ float process_query(
    int v, const float* __restrict__ lcoords,
    const float4* s_pts, const int* s_idx, int padded,
    bool use_smem, int N) {
    const float x = lcoords[3 * v + 0];
    const float y = lcoords[3 * v + 1];
    const float z = lcoords[3 * v + 2];
    const float l2 = sum_sq_ref(x, y, z);

    unsigned long long b0 = ~0ull, b1 = ~0ull, b2 = ~0ull, b3 = ~0ull;
    if (use_smem) {
        for (int j = 0; j < padded; j += 4) {
            float4 p0 = s_pts[j + 0];
            float4 p1 = s_pts[j + 1];
            float4 p2 = s_pts[j + 2];
            float4 p3 = s_pts[j + 3];
            float c0 = fmaf(z, p0.z, fmaf(y, p0.y, __fmul_rn(x, p0.x)));
            float c1 = fmaf(z, p1.z, fmaf(y, p1.y, __fmul_rn(x, p1.x)));
            float c2 = fmaf(z, p2.z, fmaf(y, p2.y, __fmul_rn(x, p2.x)));
            float c3 = fmaf(z, p3.z, fmaf(y, p3.y, __fmul_rn(x, p3.x)));
            float d0 = fmaf(-2.0f, c0, __fadd_rn(l2, p0.w));
            float d1 = fmaf(-2.0f, c1, __fadd_rn(l2, p1.w));
            float d2 = fmaf(-2.0f, c2, __fadd_rn(l2, p2.w));
            float d3 = fmaf(-2.0f, c3, __fadd_rn(l2, p3.w));
            unsigned long long k0 =
                ((unsigned long long)float_ordered(d0) << 32) | (unsigned)s_idx[j + 0];
            unsigned long long k1 =
                ((unsigned long long)float_ordered(d1) << 32) | (unsigned)s_idx[j + 1];
            unsigned long long k2 =
                ((unsigned long long)float_ordered(d2) << 32) | (unsigned)s_idx[j + 2];
            unsigned long long k3 =
                ((unsigned long long)float_ordered(d3) << 32) | (unsigned)s_idx[j + 3];
            b0 = min(b0, k0); b1 = min(b1, k1);
            b2 = min(b2, k2); b3 = min(b3, k3);
        }
    }
    unsigned long long best = min(min(b0, b1), min(b2, b3));

    // Finality: excluded true dist^2 > 156.25, slack 1.0 for rounding.
    // ordered(155.25f) = 0xC31B4000.
    if ((unsigned)(best >> 32) >= 0xC31B4000u) {
        for (int p = 0; p < N; p++) {
            float4 pt = g_pts[p];
            float c = fmaf(z, pt.z, fmaf(y, pt.y, __fmul_rn(x, pt.x)));
            float d = fmaf(-2.0f, c, __fadd_rn(l2, pt.w));
            unsigned long long k =
                ((unsigned long long)float_ordered(d) << 32) | (unsigned)p;
            best = min(best, k);
        }
    }
    return g_sal[(unsigned)best];
}

__global__ void __launch_bounds__(QBLK) query_kernel(
    const float* __restrict__ lcoords, float* __restrict__ out,
    int N, int V) {
    __shared__ float4 s_pts[SCAP];
    __shared__ int    s_idx[SCAP];

    const int cell = blockIdx.x;
    const int qcnt = g_counts[NCELL + cell];
    if (qcnt == 0) return;

    const int cz = cell >> 6, cy = (cell >> 3) & 7, cx = cell & 7;
    const int x0 = max(cx - 1, 0), x1 = min(cx + 1, GDIM - 1);
    const int y0 = max(cy - 1, 0), y1 = min(cy + 1, GDIM - 1);
    const int z0 = max(cz - 1, 0), z1 = min(cz + 1, GDIM - 1);
    const int tid  = threadIdx.x;
    const int wid  = tid >> 5;
    const int lane = tid & 31;

    // Stage neighborhood buckets -> smem. Cells distributed round-robin over
    // the 4 warps; counts are broadcast loads so every thread tracks dst.
    bool ovf = false;
    int  dst = 0, ci = 0;
    for (int dz = z0; dz <= z1; dz++)
        for (int dy = y0; dy <= y1; dy++)
            for (int dx = x0; dx <= x1; dx++) {
                int c = (dz * GDIM + dy) * GDIM + dx;
                int cnt = g_counts[c];
                ovf |= (cnt > CAP_R);
                cnt = min(cnt, CAP_R);
                if (((ci++) & 3) == wid && dst + cnt <= SCAP) {
                    for (int i = lane; i < cnt; i += 32) {
                        s_pts[dst + i] = g_rbucket[c * CAP_R + i];
                        s_idx[dst + i] = g_rbidx[c * CAP_R + i];
                    }
                }
                dst += cnt;
            }
    const int  total    = dst;
    const bool use_smem = !ovf && (total <= SCAP - 4);
    const int  padded   = (total + 3) & ~3;
    if (use_smem && tid < padded - total) {
        s_pts[total + tid] = make_float4(0.f, 0.f, 0.f, CUDART_INF_F);
        s_idx[total + tid] = 0;
    }
    __syncthreads();

    if (qcnt <= CAP_Q) {
        for (int q = tid; q < qcnt; q += QBLK) {
            int v = g_qbucket[cell * CAP_Q + q];
            out[v] = process_query(v, lcoords, s_pts, s_idx, padded, use_smem, N);
        }
    } else {
        // Query-bucket overflow (prob ~0): find this cell's queries by scan.
        for (int v = tid; v < V; v += QBLK)
            if (g_qcell[v] == cell)
                out[v] = process_query(v, lcoords, s_pts, s_idx, padded, use_smem, N);
    }
}

extern "C" void kernel_launch(void* const* d_in, const int* in_sizes, int n_in,
                              void* d_out, int out_size) {
    const float* feat    = (const float*)d_in[0];   // [N, 64]
    const float* lcoords = (const float*)d_in[1];   // [V, 3]
    const float* rcoords = (const float*)d_in[2];   // [N, 3]
    float* out = (float*)d_out;                     // [V]

    int N = in_sizes[0] / 64;
    int V = in_sizes[1] / 3;
    int NV = N + V;

    void* counts_ptr = nullptr;
    cudaGetSymbolAddress(&counts_ptr, g_counts);
    cudaMemsetAsync(counts_ptr, 0, 2 * NCELL * sizeof(int), 0);

    prep_kernel<<<(NV + PB - 1) / PB, PB>>>(feat, rcoords, lcoords, N, V);
    query_kernel<<<NCELL, QBLK>>>(lcoords, out, N, V);
}